// round 13
// baseline (speedup 1.0000x reference)
#include <cuda_runtime.h>
#include <math.h>
#include <stdint.h>

#define BATCH 256
#define VOCAB 128000
#define CAP   4096
#define CAP2  49152
#define NEG_INF __int_as_float(0xff800000)
typedef unsigned long long ull;

// ---------------- scratch (device globals; no allocations allowed) ----------
__device__ float    g_l1[BATCH*32];       // level-1 bucket masses
__device__ ull      g_bnd[(size_t)BATCH*CAP2]; // boundary-bucket elems (x, v)
__device__ int      g_bcount[BATCH];
__device__ int      g_h1done[BATCH];
__device__ unsigned g_rmk[BATCH];         // okey(row max value)
__device__ unsigned g_amin[BATCH];        // argmax (first occurrence)
__device__ ull      g_best[BATCH];        // (okey(score)<<32)|~v
__device__ int      g_B1[BATCH];          // level-1 boundary bucket
__device__ double   g_cumA1[BATCH];       // mass strictly above bucket B1
__device__ double   g_Z[BATCH];

// monotone float<->uint key (total order)
__device__ __forceinline__ unsigned okey(float f){
    unsigned b = __float_as_uint(f);
    return b ^ ((b & 0x80000000u) ? 0xFFFFFFFFu : 0x80000000u);
}
__device__ __forceinline__ float key_to_float(unsigned k){
    unsigned b = (k & 0x80000000u) ? (k ^ 0x80000000u) : ~k;
    return __uint_as_float(b);
}
__device__ __forceinline__ float ex2(float x){      // single MUFU.EX2
    float r; asm("ex2.approx.f32 %0, %1;" : "=f"(r) : "f"(x)); return r;
}

// bucket machinery — IDENTICAL formula everywhere:
//   u = rn(xmax-x); q = rn(u*cq), cq = rn(1.28/ts); qq = (int)rn(q*32) in [0,1024)
// q >= 32 excluded (mass < V*e^-25 ~ 2e-6 rel).
__device__ __forceinline__ bool qindex(float x, float xmax, float cq, int &qq){
    float u = __fadd_rn(xmax, -x);
    float q = __fmul_rn(u, cq);
    if (q >= 32.0f) return false;
    qq = (int)__fmul_rn(q, 32.0f);
    return true;
}

// jax threefry2x32-20, key = (0, 42)
__device__ __forceinline__ void threefry(unsigned c0, unsigned c1,
                                         unsigned &o0, unsigned &o1){
    const unsigned k0 = 0u, k1 = 42u;
    const unsigned k2 = 0x1BD11BDAu ^ k0 ^ k1;
    unsigned x0 = c0 + k0, x1 = c1 + k1;
#define TFR(r) { x0 += x1; x1 = ((x1 << r) | (x1 >> (32 - r))); x1 ^= x0; }
    TFR(13) TFR(15) TFR(26) TFR(6)   x0 += k1; x1 += k2 + 1u;
    TFR(17) TFR(29) TFR(16) TFR(24)  x0 += k2; x1 += k0 + 2u;
    TFR(13) TFR(15) TFR(26) TFR(6)   x0 += k0; x1 += k1 + 3u;
    TFR(17) TFR(29) TFR(16) TFR(24)  x0 += k1; x1 += k2 + 4u;
    TFR(13) TFR(15) TFR(26) TFR(6)   x0 += k2; x1 += k0 + 5u;
#undef TFR
    o0 = x0; o1 = x1;
}
__device__ __forceinline__ unsigned jax_bits32(unsigned i){
    unsigned o0, o1; threefry(0u, i, o0, o1); return o0 ^ o1;
}
__device__ __forceinline__ float gumbel_from_bits(unsigned bits){
    float u = __uint_as_float((bits >> 9) | 0x3f800000u) - 1.0f;
    if (u <= 0.0f) u = 1.17549435e-38f;
    float inner = -log1pf(u - 1.0f);   // == -log(u) exactly
    return -logf(inner);
}

// ---------------- K0: init ---------------------------------------------------
__global__ void k_init(){
    int id = blockIdx.x * 1024 + threadIdx.x;
    if (id < BATCH*32) g_l1[id] = 0.0f;
    if (id < BATCH){
        g_rmk[id] = 0u; g_amin[id] = 0xFFFFFFFFu;
        g_best[id] = 0ULL; g_bcount[id] = 0; g_h1done[id] = 0;
    }
}

// ---------------- K1: row max (batch-8 loads) --------------------------------
__global__ void k_max(const float* __restrict__ logits){
    int row = blockIdx.y, part = blockIdx.x;      // 4 parts of 32000
    const float4* x4 = (const float4*)(logits + (size_t)row * VOCAB + part * 32000);
    float vmax = NEG_INF;
    for (int base = threadIdx.x; base < 8000; base += 4096){
        float4 f[8]; bool ok[8];
#pragma unroll
        for (int k = 0; k < 8; k++){
            int i = base + k * 512;
            ok[k] = (i < 8000);
            if (ok[k]) f[k] = x4[i];
        }
#pragma unroll
        for (int k = 0; k < 8; k++){
            if (!ok[k]) continue;
            vmax = fmaxf(vmax, fmaxf(fmaxf(f[k].x, f[k].y), fmaxf(f[k].z, f[k].w)));
        }
    }
    __shared__ float sm[512];
    sm[threadIdx.x] = vmax; __syncthreads();
    for (int s = 256; s > 0; s >>= 1){
        if (threadIdx.x < s) sm[threadIdx.x] = fmaxf(sm[threadIdx.x], sm[threadIdx.x + s]);
        __syncthreads();
    }
    if (threadIdx.x == 0) atomicMax(&g_rmk[row], okey(sm[0]));
}

// ---------------- K2: level-1 histogram + fused scan (last block) ------------
__global__ void k_h1(const float* __restrict__ logits,
                     const float* __restrict__ temps,
                     const float* __restrict__ topps){
    int row = blockIdx.y;                          // 8 parts of 16000
    __shared__ float hist[32*256];                 // slot = bucket*256+tid
    __shared__ bool sLast;
    int tid = threadIdx.x;
    for (int i = tid; i < 8192; i += 256) hist[i] = 0.0f;
    __syncthreads();

    float t = temps[row]; float ts = (t == 0.0f) ? 1.0f : t;
    float xmax = key_to_float(g_rmk[row]);
    float cq  = __fdiv_rn(1.28f, ts);
    float c1n = __fdiv_rn(-1.4426950408889634f, ts);   // -log2e/ts
    const float4* x4 = (const float4*)(logits + (size_t)row * VOCAB + blockIdx.x * 16000);

    for (int base = tid; base < 4000; base += 2048){
        float4 f[8]; bool ok[8];
#pragma unroll
        for (int k = 0; k < 8; k++){
            int i = base + k * 256;
            ok[k] = (i < 4000);
            if (ok[k]) f[k] = x4[i];
        }
#pragma unroll
        for (int k = 0; k < 8; k++){
            if (!ok[k]) continue;
            float vals[4] = {f[k].x, f[k].y, f[k].z, f[k].w};
#pragma unroll
            for (int j = 0; j < 4; j++){
                float x = vals[j];
                int qq;
                if (qindex(x, xmax, cq, qq)){
                    float w = ex2(__fmul_rn(__fadd_rn(xmax, -x), c1n));
                    hist[(qq >> 5) * 256 + tid] += w;
                }
            }
        }
    }
    __syncthreads();
    int bk = tid & 31, g = tid >> 5, lane = tid & 31;
    float part_sum = 0.0f;
#pragma unroll
    for (int k = 0; k < 32; k++){
        int idx = g * 32 + ((k + lane) & 31);
        part_sum += hist[bk * 256 + idx];
    }
    if (part_sum != 0.0f) atomicAdd(&g_l1[row * 32 + bk], part_sum);

    // last block of this row computes the level-1 scan (fused k_s1)
    if (tid == 0){
        __threadfence();
        sLast = (atomicAdd(&g_h1done[row], 1) == 7);
    }
    __syncthreads();
    if (sLast && tid < 32){
        double m = (double)__ldcg(&g_l1[row * 32 + tid]);
        double Z = m;
        for (int o = 16; o > 0; o >>= 1) Z += __shfl_xor_sync(0xFFFFFFFFu, Z, o);
        float p = fminf(fmaxf(topps[row], 0.0f), 1.0f);
        double pZ = (double)p * Z;
        double run = 0.0, cA = 0.0; int B = -1;
        for (int b = 0; b < 32; b++){
            double mb = __shfl_sync(0xFFFFFFFFu, m, b);
            if (B < 0 && run + mb > pZ){ B = b; cA = run; }
            if (B < 0) run += mb;
        }
        if (B < 0){ B = 31; cA = run - __shfl_sync(0xFFFFFFFFu, m, 31); }
        if (tid == 0){ g_B1[row] = B; g_cumA1[row] = cA; g_Z[row] = Z; }
    }
}

// ---------------- K3: stream — keeps (<B1) gumbel'd (4-wide ILP), boundary buffered
__global__ void __launch_bounds__(256, 4)
k_stream(const float* __restrict__ logits,
         const float* __restrict__ temps){
    int row = blockIdx.y;
    int tid = threadIdx.x, warp = tid >> 5, lane = tid & 31;
    unsigned lmask = (1u << lane) - 1u;
    float t = temps[row]; float ts = (t == 0.0f) ? 1.0f : t;
    float xmaxv = key_to_float(g_rmk[row]);
    float cq = __fdiv_rn(1.28f, ts);
    int KB = g_B1[row] << 5;                         // qq < KB => sure keep
    int base0 = blockIdx.x * 16000;
    const float4* x4 = (const float4*)(logits + (size_t)row * VOCAB + base0);
    ull* bndRow = g_bnd + (size_t)row * CAP2;
    unsigned iBase = (unsigned)row * (unsigned)VOCAB;

    __shared__ ull sbuf[8 * 256];                    // 16KB warp-private
    int wb = warp * 256;
    ull bestp = 0ULL;

    for (int t0 = 0; t0 < 4000; t0 += 512){
        float xs[8]; bool kept[8], bnf[8];
#pragma unroll
        for (int k = 0; k < 2; k++){
            int i = t0 + tid + k * 256;
            float4 f = (i < 4000) ? x4[i]
                                  : make_float4(NEG_INF, NEG_INF, NEG_INF, NEG_INF);
            xs[k*4+0] = f.x; xs[k*4+1] = f.y; xs[k*4+2] = f.z; xs[k*4+3] = f.w;
        }
#pragma unroll
        for (int e = 0; e < 8; e++){
            int k = e >> 2, j = e & 3;
            int i = t0 + tid + k * 256;
            bool valid = (i < 4000);
            float x = xs[e];
            unsigned v = (unsigned)(base0 + i * 4 + j);
            kept[e] = false; bnf[e] = false;
            int qq;
            if (valid && qindex(x, xmaxv, cq, qq)){
                kept[e] = (qq < KB);
                bnf[e]  = (!kept[e]) && (qq < KB + 32);  // boundary bucket
            }
            if (valid && x == xmaxv) atomicMin(&g_amin[row], v);
        }
        // warp-aggregated boundary append + keep compaction
        unsigned cnt = 0;
#pragma unroll
        for (int e = 0; e < 8; e++){
            int k = e >> 2, j = e & 3;
            int i = t0 + tid + k * 256;
            unsigned v = (unsigned)(base0 + i * 4 + j);
            unsigned bb = __ballot_sync(0xFFFFFFFFu, bnf[e]);
            if (bb){
                int ldr = __ffs(bb) - 1;
                int b0;
                if (lane == ldr) b0 = atomicAdd(&g_bcount[row], __popc(bb));
                b0 = __shfl_sync(0xFFFFFFFFu, b0, ldr);
                if (bnf[e]){
                    int pos = b0 + __popc(bb & lmask);
                    if (pos < CAP2)
                        bndRow[pos] = ((ull)__float_as_uint(xs[e]) << 32) | v;
                }
            }
            unsigned bal = __ballot_sync(0xFFFFFFFFu, kept[e]);
            if (kept[e])
                sbuf[wb + cnt + __popc(bal & lmask)] =
                    ((ull)__float_as_uint(xs[e]) << 32) | v;
            cnt += __popc(bal);
        }
        // dense gumbel over compacted keeps — 4 independent chains per lane
        for (unsigned i = lane; i < cnt; i += 128){
            ull ee[4];
#pragma unroll
            for (int q = 0; q < 4; q++){
                unsigned idx = i + (unsigned)q * 32u;
                // pad: x=-inf (okey tiny), v=~0 (~v=0) — always loses
                ee[q] = (idx < cnt) ? sbuf[wb + idx]
                                    : ((ull)0xFF800000u << 32) | 0xFFFFFFFFu;
            }
            float ss[4]; unsigned bts[4];
#pragma unroll
            for (int q = 0; q < 4; q++)
                ss[q] = __fdiv_rn(__uint_as_float((unsigned)(ee[q] >> 32)), ts);
#pragma unroll
            for (int q = 0; q < 4; q++)
                bts[q] = jax_bits32(iBase + (unsigned)ee[q]);
#pragma unroll
            for (int q = 0; q < 4; q++){
                float sc = ss[q] + gumbel_from_bits(bts[q]);
                ull p = ((ull)okey(sc) << 32) | (unsigned)(~(unsigned)ee[q]);
                if (p > bestp) bestp = p;
            }
        }
    }
    for (int o = 16; o > 0; o >>= 1){
        ull other = __shfl_xor_sync(0xFFFFFFFFu, bestp, o);
        if (other > bestp) bestp = other;
    }
    if (lane == 0 && bestp != 0ULL) atomicMax(&g_best[row], bestp);
}

// ---------------- K4: per-row — level-2 from buffer, cut, sample, output -----
__global__ void k_mid(const float* __restrict__ logits,
                      const float* __restrict__ temps,
                      const float* __restrict__ topps,
                      float* __restrict__ out){
    int row = blockIdx.x, tid = threadIdx.x;
    int warp = tid >> 5;
    __shared__ float h2s[1024];                // warp*32+sub; reused as sli
    __shared__ ull keys[CAP];                  // 32KB
    __shared__ double sarr[1024];
    __shared__ ull sp[1024];
    __shared__ float svf[1024];
    __shared__ int sB2, scnt;
    __shared__ double sCA2;
    __shared__ ull sC;

    float t = temps[row]; float ts = (t == 0.0f) ? 1.0f : t;
    unsigned kmax = g_rmk[row];
    float xmaxv = key_to_float(kmax);
    float Ms = __fdiv_rn(xmaxv, ts);
    float cq = __fdiv_rn(1.28f, ts);
    int B1 = g_B1[row];
    double cumA1 = g_cumA1[row];
    double Z = g_Z[row];
    float p = fminf(fmaxf(topps[row], 0.0f), 1.0f);
    double pZ = (double)p * Z;
    int nb = min(g_bcount[row], CAP2);
    const ull* bnd = g_bnd + (size_t)row * CAP2;
    unsigned iBase = (unsigned)row * (unsigned)VOCAB;
    float c1n = __fdiv_rn(-1.4426950408889634f, ts);

    // ---- level-2 histogram from buffer ----
    h2s[tid] = 0.0f;
    __syncthreads();
    for (int i = tid; i < nb; i += 1024){
        ull e = bnd[i];
        float x = __uint_as_float((unsigned)(e >> 32));
        int qq; qindex(x, xmaxv, cq, qq);
        float w = ex2(__fmul_rn(__fadd_rn(xmaxv, -x), c1n));
        atomicAdd(&h2s[warp * 32 + (qq & 31)], w);
    }
    __syncthreads();
    if (tid < 32){
        double m = 0.0;
        for (int w = 0; w < 32; w++) m += (double)h2s[w * 32 + tid];
        double run = cumA1, cA = cumA1; int B = -1;
        for (int b = 0; b < 32; b++){
            double mb = __shfl_sync(0xFFFFFFFFu, m, b);
            if (B < 0 && run + mb > pZ){ B = b; cA = run; }
            if (B < 0) run += mb;
        }
        if (B < 0){ B = 31; cA = run - __shfl_sync(0xFFFFFFFFu, m, 31); }
        if (tid == 0){ sB2 = B; sCA2 = cA; scnt = 0; }
    }
    __syncthreads();
    int B2 = sB2; double cumAbove = sCA2;
    int Qcut = B1 * 32 + B2;
    int* sli = (int*)h2s;                      // reuse (h2s dead now)

    // ---- gather sub==B2 candidates; gumbel over kept subs (<B2) ----
    ull bestp = 0ULL; float sk = 0.0f;
    for (int i = tid; i < nb; i += 1024){
        ull e = bnd[i];
        float x = __uint_as_float((unsigned)(e >> 32));
        unsigned v = (unsigned)e;
        int qq; qindex(x, xmaxv, cq, qq);
        int sub = qq & 31;
        if (sub == B2){
            int pos = atomicAdd(&scnt, 1);
            if (pos < CAP){
                float s = __fdiv_rn(x, ts);
                keys[pos] = ((ull)okey(s) << 32) | v;
            }
        } else if (sub < B2){
            float s = __fdiv_rn(x, ts);
            float sc = s + gumbel_from_bits(jax_bits32(iBase + v));
            ull pk = ((ull)okey(sc) << 32) | (unsigned)(~v);
            if (pk > bestp) bestp = pk;
        }
    }
    __syncthreads();
    int count = min(scnt, CAP);

    // ---- sort + exact cut within sub-bucket ----
    if (count == 0){
        if (tid == 0) sC = 0ULL;
    } else {
        int n = 1; while (n < count) n <<= 1; if (n < 2) n = 2;
        for (int i = tid; i < n; i += 1024)
            if (i >= count) keys[i] = 0ULL;
        __syncthreads();
        for (int k2 = 2; k2 <= n; k2 <<= 1){
            for (int j = k2 >> 1; j > 0; j >>= 1){
                for (int i = tid; i < n; i += 1024){
                    int ixj = i ^ j;
                    if (ixj > i){
                        ull a = keys[i], b = keys[ixj];
                        bool seg = ((i & k2) == 0);
                        if (seg ? (a < b) : (a > b)){ keys[i] = b; keys[ixj] = a; }
                    }
                }
                __syncthreads();
            }
        }
        int m = (n + 1023) / 1024;   // <= 4
        int lo = tid * m;
        double ev[4];
        double ls = 0.0;
        for (int q = 0; q < m; q++){
            int i = lo + q; double e = 0.0;
            if (i < count){
                double sv2 = (double)key_to_float((unsigned)(keys[i] >> 32));
                e = exp(sv2 - (double)Ms);
            }
            ev[q] = e; ls += e;
        }
        sarr[tid] = ls; __syncthreads();
        for (int off = 1; off < 1024; off <<= 1){
            double v = sarr[tid];
            double a = (tid >= off) ? sarr[tid - off] : 0.0;
            __syncthreads();
            sarr[tid] = v + a;
            __syncthreads();
        }
        double run = sarr[tid] - ls + cumAbove;
        int lastKept = -1;
        for (int q = 0; q < m; q++){
            int i = lo + q;
            run += ev[q];
            if (i < count && run <= pZ) lastKept = i;
        }
        sli[tid] = lastKept; __syncthreads();
        for (int s2 = 512; s2 > 0; s2 >>= 1){
            if (tid < s2) sli[tid] = max(sli[tid], sli[tid + s2]);
            __syncthreads();
        }
        if (tid == 0){
            int iL = sli[0];
            ull C;
            if (iL >= 0)             C = keys[iL];
            else if (cumAbove > 0.0) C = keys[0] + 1ULL;   // cut above all cands
            else                     C = keys[0];          // force-keep top
            sC = C;
        }
    }
    __syncthreads();
    ull C = sC;

    // ---- kept candidates: gumbel + mass ----
    for (int i = tid; i < count; i += 1024){
        ull e = keys[i];
        if (e >= C){
            unsigned v = (unsigned)e;
            float s = key_to_float((unsigned)(e >> 32));
            sk += __expf(s - Ms);
            float sc = s + gumbel_from_bits(jax_bits32(iBase + v));
            ull pk = ((ull)okey(sc) << 32) | (unsigned)(~v);
            if (pk > bestp) bestp = pk;
        }
    }
    sp[tid] = bestp; svf[tid] = sk;
    __syncthreads();
    for (int s = 512; s > 0; s >>= 1){
        if (tid < s){
            if (sp[tid + s] > sp[tid]) sp[tid] = sp[tid + s];
            svf[tid] += svf[tid + s];
        }
        __syncthreads();
    }

    if (tid == 0){
        ull bestAll = g_best[row];
        if (sp[0] > bestAll) bestAll = sp[0];
        double skAll = cumAbove + (double)svf[0];
        unsigned greedy = g_amin[row];
        unsigned tok;
        if (t == 0.0f) tok = greedy;
        else {
            unsigned cand = ~(unsigned)(bestAll & 0xFFFFFFFFu);
            tok = (cand < (unsigned)VOCAB) ? cand : greedy;
        }
        float xtok = logits[(size_t)row * VOCAB + tok];
        float stok = __fdiv_rn(xtok, ts);
        int qq; bool sure = qindex(xtok, xmaxv, cq, qq) && (qq < Qcut);
        ull pT = ((ull)okey(stok) << 32) | tok;
        float sel = (sure || pT >= C) ? stok : NEG_INF;
        double lz = (double)Ms + log(skAll);
        out[row]          = (float)tok;
        out[BATCH + row]  = (float)((double)sel - lz);
    }
}

// ---------------- launch -----------------------------------------------------
extern "C" void kernel_launch(void* const* d_in, const int* in_sizes, int n_in,
                              void* d_out, int out_size){
    const float* logits = (const float*)d_in[0];
    const float* temps  = (const float*)d_in[1];
    const float* topps  = (const float*)d_in[2];
    float* out = (float*)d_out;

    k_init  <<<16, 1024>>>();
    k_max   <<<dim3(4, BATCH), 512>>>(logits);
    k_h1    <<<dim3(8, BATCH), 256>>>(logits, temps, topps);
    k_stream<<<dim3(8, BATCH), 256>>>(logits, temps);
    k_mid   <<<BATCH, 1024>>>(logits, temps, topps, out);
}

// round 14
// speedup vs baseline: 1.4455x; 1.4455x over previous
#include <cuda_runtime.h>
#include <math.h>
#include <stdint.h>

#define BATCH 256
#define VOCAB 128000
#define CAP   4096
#define NEG_INF __int_as_float(0xff800000)
typedef unsigned long long ull;

// ---------------- scratch (device globals; no allocations allowed) ----------
__device__ float    g_l1[BATCH*32];       // level-1 bucket masses
__device__ float    g_l2[BATCH*32];       // level-2 bucket masses
__device__ ull      g_cand[BATCH*CAP];    // boundary sub-bucket candidates
__device__ int      g_ccount[BATCH];
__device__ int      g_h1done[BATCH];
__device__ int      g_h2done[BATCH];
__device__ unsigned g_rmk[BATCH];         // okey(row max value)
__device__ unsigned g_amin[BATCH];        // argmax (first occurrence)
__device__ ull      g_best[BATCH];        // (okey(score)<<32)|~v
__device__ int      g_B1[BATCH];          // level-1 boundary bucket
__device__ int      g_Qcut[BATCH];        // global sub-bucket cut index
__device__ double   g_cumA1[BATCH];       // mass strictly above bucket B1
__device__ double   g_cumA2[BATCH];       // mass strictly above final sub-bucket
__device__ double   g_Z[BATCH];

// monotone float<->uint key (total order)
__device__ __forceinline__ unsigned okey(float f){
    unsigned b = __float_as_uint(f);
    return b ^ ((b & 0x80000000u) ? 0xFFFFFFFFu : 0x80000000u);
}
__device__ __forceinline__ float key_to_float(unsigned k){
    unsigned b = (k & 0x80000000u) ? (k ^ 0x80000000u) : ~k;
    return __uint_as_float(b);
}
__device__ __forceinline__ float ex2(float x){      // single MUFU.EX2
    float r; asm("ex2.approx.f32 %0, %1;" : "=f"(r) : "f"(x)); return r;
}

// bucket machinery — IDENTICAL formula everywhere:
//   u = rn(xmax-x); q = rn(u*cq), cq = rn(1.28/ts); qq = (int)rn(q*32) in [0,1024)
// q >= 32 excluded (mass < V*e^-25 ~ 2e-6 rel).
__device__ __forceinline__ bool qindex(float x, float xmax, float cq, int &qq){
    float u = __fadd_rn(xmax, -x);
    float q = __fmul_rn(u, cq);
    if (q >= 32.0f) return false;
    qq = (int)__fmul_rn(q, 32.0f);
    return true;
}

// jax threefry2x32-20, key = (0, 42)
__device__ __forceinline__ void threefry(unsigned c0, unsigned c1,
                                         unsigned &o0, unsigned &o1){
    const unsigned k0 = 0u, k1 = 42u;
    const unsigned k2 = 0x1BD11BDAu ^ k0 ^ k1;
    unsigned x0 = c0 + k0, x1 = c1 + k1;
#define TFR(r) { x0 += x1; x1 = ((x1 << r) | (x1 >> (32 - r))); x1 ^= x0; }
    TFR(13) TFR(15) TFR(26) TFR(6)   x0 += k1; x1 += k2 + 1u;
    TFR(17) TFR(29) TFR(16) TFR(24)  x0 += k2; x1 += k0 + 2u;
    TFR(13) TFR(15) TFR(26) TFR(6)   x0 += k0; x1 += k1 + 3u;
    TFR(17) TFR(29) TFR(16) TFR(24)  x0 += k1; x1 += k2 + 4u;
    TFR(13) TFR(15) TFR(26) TFR(6)   x0 += k2; x1 += k0 + 5u;
#undef TFR
    o0 = x0; o1 = x1;
}
__device__ __forceinline__ unsigned jax_bits32(unsigned i){
    unsigned o0, o1; threefry(0u, i, o0, o1); return o0 ^ o1;
}
__device__ __forceinline__ float gumbel_from_bits(unsigned bits){
    float u = __uint_as_float((bits >> 9) | 0x3f800000u) - 1.0f;
    if (u <= 0.0f) u = 1.17549435e-38f;
    float inner = -log1pf(u - 1.0f);   // == -log(u) exactly
    return -logf(inner);
}

// ---------------- K0: init ---------------------------------------------------
__global__ void k_init(){
    int id = blockIdx.x * 1024 + threadIdx.x;
    if (id < BATCH*32){ g_l1[id] = 0.0f; g_l2[id] = 0.0f; }
    if (id < BATCH){
        g_rmk[id] = 0u; g_amin[id] = 0xFFFFFFFFu;
        g_best[id] = 0ULL; g_ccount[id] = 0;
        g_h1done[id] = 0; g_h2done[id] = 0;
    }
}

// ---------------- K1: row max (batch-8 loads) --------------------------------
__global__ void k_max(const float* __restrict__ logits){
    int row = blockIdx.y, part = blockIdx.x;      // 4 parts of 32000
    const float4* x4 = (const float4*)(logits + (size_t)row * VOCAB + part * 32000);
    float vmax = NEG_INF;
    for (int base = threadIdx.x; base < 8000; base += 4096){
        float4 f[8]; bool ok[8];
#pragma unroll
        for (int k = 0; k < 8; k++){
            int i = base + k * 512;
            ok[k] = (i < 8000);
            if (ok[k]) f[k] = x4[i];
        }
#pragma unroll
        for (int k = 0; k < 8; k++){
            if (!ok[k]) continue;
            vmax = fmaxf(vmax, fmaxf(fmaxf(f[k].x, f[k].y), fmaxf(f[k].z, f[k].w)));
        }
    }
    __shared__ float sm[512];
    sm[threadIdx.x] = vmax; __syncthreads();
    for (int s = 256; s > 0; s >>= 1){
        if (threadIdx.x < s) sm[threadIdx.x] = fmaxf(sm[threadIdx.x], sm[threadIdx.x + s]);
        __syncthreads();
    }
    if (threadIdx.x == 0) atomicMax(&g_rmk[row], okey(sm[0]));
}

// ---------------- K2: level-1 histogram + fused scan (last block) ------------
__global__ void k_h1(const float* __restrict__ logits,
                     const float* __restrict__ temps,
                     const float* __restrict__ topps){
    int row = blockIdx.y;                          // 8 parts of 16000
    __shared__ float hist[32*256];                 // slot = bucket*256+tid
    __shared__ bool sLast;
    int tid = threadIdx.x;
    for (int i = tid; i < 8192; i += 256) hist[i] = 0.0f;
    __syncthreads();

    float t = temps[row]; float ts = (t == 0.0f) ? 1.0f : t;
    float xmax = key_to_float(g_rmk[row]);
    float cq  = __fdiv_rn(1.28f, ts);
    float c1n = __fdiv_rn(-1.4426950408889634f, ts);   // -log2e/ts
    const float4* x4 = (const float4*)(logits + (size_t)row * VOCAB + blockIdx.x * 16000);

    for (int base = tid; base < 4000; base += 2048){
        float4 f[8]; bool ok[8];
#pragma unroll
        for (int k = 0; k < 8; k++){
            int i = base + k * 256;
            ok[k] = (i < 4000);
            if (ok[k]) f[k] = x4[i];
        }
#pragma unroll
        for (int k = 0; k < 8; k++){
            if (!ok[k]) continue;
            float vals[4] = {f[k].x, f[k].y, f[k].z, f[k].w};
#pragma unroll
            for (int j = 0; j < 4; j++){
                float x = vals[j];
                int qq;
                if (qindex(x, xmax, cq, qq)){
                    float w = ex2(__fmul_rn(__fadd_rn(xmax, -x), c1n));
                    hist[(qq >> 5) * 256 + tid] += w;
                }
            }
        }
    }
    __syncthreads();
    int bk = tid & 31, g = tid >> 5, lane = tid & 31;
    float part_sum = 0.0f;
#pragma unroll
    for (int k = 0; k < 32; k++){
        int idx = g * 32 + ((k + lane) & 31);
        part_sum += hist[bk * 256 + idx];
    }
    if (part_sum != 0.0f) atomicAdd(&g_l1[row * 32 + bk], part_sum);

    if (tid == 0){
        __threadfence();
        sLast = (atomicAdd(&g_h1done[row], 1) == 7);
    }
    __syncthreads();
    if (sLast && tid < 32){
        double m = (double)__ldcg(&g_l1[row * 32 + tid]);
        double Z = m;
        for (int o = 16; o > 0; o >>= 1) Z += __shfl_xor_sync(0xFFFFFFFFu, Z, o);
        float p = fminf(fmaxf(topps[row], 0.0f), 1.0f);
        double pZ = (double)p * Z;
        double run = 0.0, cA = 0.0; int B = -1;
        for (int b = 0; b < 32; b++){
            double mb = __shfl_sync(0xFFFFFFFFu, m, b);
            if (B < 0 && run + mb > pZ){ B = b; cA = run; }
            if (B < 0) run += mb;
        }
        if (B < 0){ B = 31; cA = run - __shfl_sync(0xFFFFFFFFu, m, 31); }
        if (tid == 0){ g_B1[row] = B; g_cumA1[row] = cA; g_Z[row] = Z; }
    }
}

// ---------------- K3: level-2 histogram (gated on B1) + fused scan -----------
__global__ void k_h2(const float* __restrict__ logits,
                     const float* __restrict__ temps,
                     const float* __restrict__ topps){
    int row = blockIdx.y;                          // 8 parts of 16000
    __shared__ float hist[32*256];
    __shared__ bool sLast;
    int tid = threadIdx.x;
    for (int i = tid; i < 8192; i += 256) hist[i] = 0.0f;
    __syncthreads();

    float t = temps[row]; float ts = (t == 0.0f) ? 1.0f : t;
    float xmax = key_to_float(g_rmk[row]);
    int B1 = g_B1[row];
    float cq  = __fdiv_rn(1.28f, ts);
    float c1n = __fdiv_rn(-1.4426950408889634f, ts);
    const float4* x4 = (const float4*)(logits + (size_t)row * VOCAB + blockIdx.x * 16000);

    for (int base = tid; base < 4000; base += 2048){
        float4 f[8]; bool ok[8];
#pragma unroll
        for (int k = 0; k < 8; k++){
            int i = base + k * 256;
            ok[k] = (i < 4000);
            if (ok[k]) f[k] = x4[i];
        }
#pragma unroll
        for (int k = 0; k < 8; k++){
            if (!ok[k]) continue;
            float vals[4] = {f[k].x, f[k].y, f[k].z, f[k].w};
#pragma unroll
            for (int j = 0; j < 4; j++){
                float x = vals[j];
                int qq;
                if (qindex(x, xmax, cq, qq) && (qq >> 5) == B1){
                    float w = ex2(__fmul_rn(__fadd_rn(xmax, -x), c1n));
                    hist[(qq & 31) * 256 + tid] += w;
                }
            }
        }
    }
    __syncthreads();
    int bk = tid & 31, g = tid >> 5, lane = tid & 31;
    float part_sum = 0.0f;
#pragma unroll
    for (int k = 0; k < 32; k++){
        int idx = g * 32 + ((k + lane) & 31);
        part_sum += hist[bk * 256 + idx];
    }
    if (part_sum != 0.0f) atomicAdd(&g_l2[row * 32 + bk], part_sum);

    if (tid == 0){
        __threadfence();
        sLast = (atomicAdd(&g_h2done[row], 1) == 7);
    }
    __syncthreads();
    if (sLast && tid < 32){
        double m = (double)__ldcg(&g_l2[row * 32 + tid]);
        double Z = g_Z[row];
        float p = fminf(fmaxf(topps[row], 0.0f), 1.0f);
        double pZ = (double)p * Z;
        double run = g_cumA1[row], cA = run; int B = -1;
        for (int b = 0; b < 32; b++){
            double mb = __shfl_sync(0xFFFFFFFFu, m, b);
            if (B < 0 && run + mb > pZ){ B = b; cA = run; }
            if (B < 0) run += mb;
        }
        if (B < 0){ B = 31; cA = run - __shfl_sync(0xFFFFFFFFu, m, 31); }
        if (tid == 0){
            g_Qcut[row] = g_B1[row] * 32 + B;
            g_cumA2[row] = cA;
        }
    }
}

// ---------------- K4: stream — exact keeps, deferred dense ILP gumbel --------
__global__ void __launch_bounds__(256, 4)
k_stream(const float* __restrict__ logits,
         const float* __restrict__ temps){
    int row = blockIdx.y;
    int tid = threadIdx.x, warp = tid >> 5, lane = tid & 31;
    unsigned lmask = (1u << lane) - 1u;
    float t = temps[row]; float ts = (t == 0.0f) ? 1.0f : t;
    float xmaxv = key_to_float(g_rmk[row]);
    float cq = __fdiv_rn(1.28f, ts);
    int Qcut = g_Qcut[row];
    int base0 = blockIdx.x * 16000;
    const float4* x4 = (const float4*)(logits + (size_t)row * VOCAB + base0);
    ull* candRow = g_cand + (size_t)row * CAP;
    unsigned iBase = (unsigned)row * (unsigned)VOCAB;

    __shared__ ull sbuf[8 * 512];                    // 32KB; 512-slot warp ring
    int wb = warp * 512;
    unsigned wcnt = 0;                               // warp-uniform
    ull bestp = 0ULL;

    for (int t0 = 0; t0 < 4000; t0 += 512){
        float xs[8]; bool kept[8];
#pragma unroll
        for (int k = 0; k < 2; k++){
            int i = t0 + tid + k * 256;
            float4 f = (i < 4000) ? x4[i]
                                  : make_float4(NEG_INF, NEG_INF, NEG_INF, NEG_INF);
            xs[k*4+0] = f.x; xs[k*4+1] = f.y; xs[k*4+2] = f.z; xs[k*4+3] = f.w;
        }
#pragma unroll
        for (int e = 0; e < 8; e++){
            int k = e >> 2, j = e & 3;
            int i = t0 + tid + k * 256;
            bool valid = (i < 4000);
            float x = xs[e];
            unsigned v = (unsigned)(base0 + i * 4 + j);
            kept[e] = false;
            bool cnd = false;
            int qq;
            if (valid && qindex(x, xmaxv, cq, qq)){
                kept[e] = (qq < Qcut);
                cnd     = (qq == Qcut);
            }
            // aggregated candidate append (rare)
            unsigned cb = __ballot_sync(0xFFFFFFFFu, cnd);
            if (cb){
                int ldr = __ffs(cb) - 1;
                int b0;
                if (lane == ldr) b0 = atomicAdd(&g_ccount[row], __popc(cb));
                b0 = __shfl_sync(0xFFFFFFFFu, b0, ldr);
                if (cnd){
                    int pos = b0 + __popc(cb & lmask);
                    if (pos < CAP){
                        float s = __fdiv_rn(x, ts);
                        candRow[pos] = ((ull)okey(s) << 32) | v;
                    }
                }
            }
            if (valid && x == xmaxv) atomicMin(&g_amin[row], v);
            // keep compaction into warp ring
            unsigned bal = __ballot_sync(0xFFFFFFFFu, kept[e]);
            if (kept[e])
                sbuf[wb + wcnt + __popc(bal & lmask)] =
                    ((ull)__float_as_uint(x) << 32) | v;
            wcnt += __popc(bal);
        }
        // process full 128-batches: 4 independent chains/lane, zero padding
        while (wcnt >= 128){
            wcnt -= 128;
            ull ee[4];
#pragma unroll
            for (int q = 0; q < 4; q++) ee[q] = sbuf[wb + wcnt + lane + q * 32];
            float ss[4]; unsigned bts[4];
#pragma unroll
            for (int q = 0; q < 4; q++)
                ss[q] = __fdiv_rn(__uint_as_float((unsigned)(ee[q] >> 32)), ts);
#pragma unroll
            for (int q = 0; q < 4; q++)
                bts[q] = jax_bits32(iBase + (unsigned)ee[q]);
#pragma unroll
            for (int q = 0; q < 4; q++){
                float sc = ss[q] + gumbel_from_bits(bts[q]);
                ull p = ((ull)okey(sc) << 32) | (unsigned)(~(unsigned)ee[q]);
                if (p > bestp) bestp = p;
            }
        }
    }
    // final flush (< 128 left), serial stride-32
    for (unsigned i = lane; i < wcnt; i += 32){
        ull e = sbuf[wb + i];
        unsigned v = (unsigned)e;
        float s = __fdiv_rn(__uint_as_float((unsigned)(e >> 32)), ts);
        float sc = s + gumbel_from_bits(jax_bits32(iBase + v));
        ull p = ((ull)okey(sc) << 32) | (unsigned)(~v);
        if (p > bestp) bestp = p;
    }
    for (int o = 16; o > 0; o >>= 1){
        ull other = __shfl_xor_sync(0xFFFFFFFFu, bestp, o);
        if (other > bestp) bestp = other;
    }
    if (lane == 0 && bestp != 0ULL) atomicMax(&g_best[row], bestp);
}

// ---------------- K5: per-row finalize — sort cands, cut, sample, output -----
__global__ void k_mid(const float* __restrict__ logits,
                      const float* __restrict__ temps,
                      const float* __restrict__ topps,
                      float* __restrict__ out){
    int row = blockIdx.x, tid = threadIdx.x;
    __shared__ ull keys[CAP];                  // 32KB
    __shared__ double sarr[1024];
    __shared__ int sli[1024];
    __shared__ ull sC;

    float t = temps[row]; float ts = (t == 0.0f) ? 1.0f : t;
    unsigned kmax = g_rmk[row];
    float xmaxv = key_to_float(kmax);
    float Ms = __fdiv_rn(xmaxv, ts);
    float cq = __fdiv_rn(1.28f, ts);
    int Qcut = g_Qcut[row];
    double cumAbove = g_cumA2[row];
    double pZ = (double)fminf(fmaxf(topps[row], 0.0f), 1.0f) * g_Z[row];
    int count = min(g_ccount[row], CAP);
    unsigned iBase = (unsigned)row * (unsigned)VOCAB;

    if (count == 0){                          // guard; ~never (bucket has mass)
        if (tid == 0) sC = 0ULL;
    } else {
        int n = 1; while (n < count) n <<= 1; if (n < 2) n = 2;
        for (int i = tid; i < n; i += 1024)
            keys[i] = (i < count) ? g_cand[(size_t)row * CAP + i] : 0ULL;
        __syncthreads();
        for (int k2 = 2; k2 <= n; k2 <<= 1){
            for (int j = k2 >> 1; j > 0; j >>= 1){
                for (int i = tid; i < n; i += 1024){
                    int ixj = i ^ j;
                    if (ixj > i){
                        ull a = keys[i], b = keys[ixj];
                        bool seg = ((i & k2) == 0);
                        if (seg ? (a < b) : (a > b)){ keys[i] = b; keys[ixj] = a; }
                    }
                }
                __syncthreads();
            }
        }
        int m = (n + 1023) / 1024;   // <= 4
        int lo = tid * m;
        double ev[4];
        double ls = 0.0;
        for (int q = 0; q < m; q++){
            int i = lo + q; double e = 0.0;
            if (i < count){
                double sv2 = (double)key_to_float((unsigned)(keys[i] >> 32));
                e = exp(sv2 - (double)Ms);
            }
            ev[q] = e; ls += e;
        }
        sarr[tid] = ls; __syncthreads();
        for (int off = 1; off < 1024; off <<= 1){
            double v = sarr[tid];
            double a = (tid >= off) ? sarr[tid - off] : 0.0;
            __syncthreads();
            sarr[tid] = v + a;
            __syncthreads();
        }
        double run = sarr[tid] - ls + cumAbove;
        int lastKept = -1;
        for (int q = 0; q < m; q++){
            int i = lo + q;
            run += ev[q];
            if (i < count && run <= pZ) lastKept = i;
        }
        sli[tid] = lastKept; __syncthreads();
        for (int s2 = 512; s2 > 0; s2 >>= 1){
            if (tid < s2) sli[tid] = max(sli[tid], sli[tid + s2]);
            __syncthreads();
        }
        if (tid == 0){
            int iL = sli[0];
            ull C;
            if (iL >= 0)             C = keys[iL];
            else if (cumAbove > 0.0) C = keys[0] + 1ULL;   // cut above all cands
            else                     C = keys[0];          // force-keep top
            sC = C;
        }
    }
    __syncthreads();
    ull C = sC;

    // kept candidates: gumbel + mass
    ull bestp = 0ULL; float sk = 0.0f;
    for (int i = tid; i < count; i += 1024){
        ull e = keys[i];
        if (e >= C){
            unsigned v = (unsigned)e;
            float s = key_to_float((unsigned)(e >> 32));
            sk += __expf(s - Ms);
            float sc = s + gumbel_from_bits(jax_bits32(iBase + v));
            ull pk = ((ull)okey(sc) << 32) | (unsigned)(~v);
            if (pk > bestp) bestp = pk;
        }
    }
    __shared__ ull sp[1024];
    __shared__ float svf[1024];
    sp[tid] = bestp; svf[tid] = sk;
    __syncthreads();
    for (int s = 512; s > 0; s >>= 1){
        if (tid < s){
            if (sp[tid + s] > sp[tid]) sp[tid] = sp[tid + s];
            svf[tid] += svf[tid + s];
        }
        __syncthreads();
    }

    if (tid == 0){
        ull bestAll = g_best[row];
        if (sp[0] > bestAll) bestAll = sp[0];
        double skAll = cumAbove + (double)svf[0];
        unsigned greedy = g_amin[row];
        unsigned tok;
        if (t == 0.0f) tok = greedy;
        else {
            unsigned cand = ~(unsigned)(bestAll & 0xFFFFFFFFu);
            tok = (cand < (unsigned)VOCAB) ? cand : greedy;
        }
        float xtok = logits[(size_t)row * VOCAB + tok];
        float stok = __fdiv_rn(xtok, ts);
        int qq; bool sure = qindex(xtok, xmaxv, cq, qq) && (qq < Qcut);
        ull pT = ((ull)okey(stok) << 32) | tok;
        float sel = (sure || pT >= C) ? stok : NEG_INF;
        double lz = (double)Ms + log(skAll);
        out[row]          = (float)tok;
        out[BATCH + row]  = (float)((double)sel - lz);
    }
}

// ---------------- launch -----------------------------------------------------
extern "C" void kernel_launch(void* const* d_in, const int* in_sizes, int n_in,
                              void* d_out, int out_size){
    const float* logits = (const float*)d_in[0];
    const float* temps  = (const float*)d_in[1];
    const float* topps  = (const float*)d_in[2];
    float* out = (float*)d_out;

    k_init  <<<16, 1024>>>();
    k_max   <<<dim3(4, BATCH), 512>>>(logits);
    k_h1    <<<dim3(8, BATCH), 256>>>(logits, temps, topps);
    k_h2    <<<dim3(8, BATCH), 256>>>(logits, temps, topps);
    k_stream<<<dim3(8, BATCH), 256>>>(logits, temps);
    k_mid   <<<BATCH, 1024>>>(logits, temps, topps, out);
}